// round 5
// baseline (speedup 1.0000x reference)
#include <cuda_runtime.h>
#include <cuda_bf16.h>

#define NF       2048
#define NROWS    8192
#define TOTQ     (NROWS * (NF / 4))   // total float4s = 4194304
#define GRID     296                  // <= 2 CTAs/SM on 148 SMs: all co-resident
#define TPB      256
#define NTHREADS (GRID * TPB)         // 75776 = 148 * 512  (multiple of row = 512 float4)
#define NPART    148                  // partials per column-quad
#define FULLIT   55                   // TOTQ / NTHREADS
#define REM      (TOTQ - FULLIT * NTHREADS)   // 26624 threads do a 56th element

// Scratch (allocation-free)
__device__ float4 g_ps[NTHREADS];     // per-thread partial sums   (1.2 MB)
__device__ float4 g_pq[NTHREADS];     // per-thread partial sumsqs (1.2 MB)
__device__ float  g_mean[NF];
__device__ float  g_istd[NF];

// Self-resetting sense-reversing grid barrier (graph-replay safe: counter
// resets to 0 every use, sense monotonically increments).
__device__ unsigned          g_count = 0;
__device__ volatile unsigned g_sense = 0;

__device__ __forceinline__ void grid_sync() {
    __threadfence();            // release: make this thread's writes visible
    __syncthreads();
    if (threadIdx.x == 0) {
        const unsigned old = g_sense;
        const unsigned arrived = atomicAdd(&g_count, 1u);
        if (arrived == GRID - 1) {
            g_count = 0;
            __threadfence();
            g_sense = old + 1;  // release the grid
        } else {
            while (g_sense == old) { __nanosleep(64); }
        }
        __threadfence();        // acquire
    }
    __syncthreads();
}

__device__ __forceinline__ void acc8(float4& s, float4& q, const float4 v) {
    s.x += v.x;       s.y += v.y;       s.z += v.z;       s.w += v.w;
    q.x += v.x * v.x; q.y += v.y * v.y; q.z += v.z * v.z; q.w += v.w * v.w;
}

__global__ void __launch_bounds__(TPB, 2) k_fused(const float* __restrict__ x,
                                                  float* __restrict__ out) {
    const int tid  = blockIdx.x * TPB + threadIdx.x;   // [0, 75776)
    const int lane = threadIdx.x & 31;

    // ---------------- Phase 1: per-thread partial sum/sumsq -----------------
    // Stride NTHREADS is a multiple of the 512-float4 row, so this thread's
    // column-quad (tid & 511) is FIXED. Default cache policy: x stays in L2.
    {
        const float4* xp = reinterpret_cast<const float4*>(x);
        float4 s = make_float4(0.f, 0.f, 0.f, 0.f);
        float4 q = make_float4(0.f, 0.f, 0.f, 0.f);
        size_t i = (size_t)tid;

        #pragma unroll 1
        for (int b = 0; b < 6; ++b) {              // 48 always-valid iters
            float4 buf[8];
            #pragma unroll
            for (int r = 0; r < 8; ++r) buf[r] = xp[i + (size_t)r * NTHREADS];
            #pragma unroll
            for (int r = 0; r < 8; ++r) acc8(s, q, buf[r]);
            i += (size_t)8 * NTHREADS;
        }
        {                                          // iters 48..54 always valid
            float4 buf[7];
            #pragma unroll
            for (int r = 0; r < 7; ++r) buf[r] = xp[i + (size_t)r * NTHREADS];
            #pragma unroll
            for (int r = 0; r < 7; ++r) acc8(s, q, buf[r]);
            i += (size_t)7 * NTHREADS;
        }
        if (tid < REM) acc8(s, q, xp[i]);          // ragged 56th iter

        g_ps[tid] = s;
        g_pq[tid] = q;
    }

    grid_sync();

    // ---------------- Phase 2: one warp per column-quad ---------------------
    // Quad qd has partials at g_ps[qd + 512*k], k in [0,148). Butterfly
    // shuffle reduce: fixed tree, deterministic. Scratch is L2-hot (2.4 MB).
    {
        const int gw = tid >> 5;                   // global warp id [0, 2368)
        if (gw < NF / 4) {
            float4 S = make_float4(0.f, 0.f, 0.f, 0.f);
            float4 Q = make_float4(0.f, 0.f, 0.f, 0.f);
            for (int k = lane; k < NPART; k += 32) {
                const float4 a = g_ps[gw + (k << 9)];
                const float4 b = g_pq[gw + (k << 9)];
                S.x += a.x; S.y += a.y; S.z += a.z; S.w += a.w;
                Q.x += b.x; Q.y += b.y; Q.z += b.z; Q.w += b.w;
            }
            #pragma unroll
            for (int o = 16; o > 0; o >>= 1) {
                S.x += __shfl_xor_sync(0xffffffffu, S.x, o);
                S.y += __shfl_xor_sync(0xffffffffu, S.y, o);
                S.z += __shfl_xor_sync(0xffffffffu, S.z, o);
                S.w += __shfl_xor_sync(0xffffffffu, S.w, o);
                Q.x += __shfl_xor_sync(0xffffffffu, Q.x, o);
                Q.y += __shfl_xor_sync(0xffffffffu, Q.y, o);
                Q.z += __shfl_xor_sync(0xffffffffu, Q.z, o);
                Q.w += __shfl_xor_sync(0xffffffffu, Q.w, o);
            }
            if (lane < 4) {
                const float sv = lane == 0 ? S.x : lane == 1 ? S.y : lane == 2 ? S.z : S.w;
                const float qv = lane == 0 ? Q.x : lane == 1 ? Q.y : lane == 2 ? Q.z : Q.w;
                const double mean = (double)sv / (double)NROWS;
                const double var  = ((double)qv - (double)sv * mean) / (double)(NROWS - 1);
                g_mean[gw * 4 + lane] = (float)mean;
                g_istd[gw * 4 + lane] = (float)(1.0 / sqrt(var + 1e-6));
            }
        }
    }

    grid_sync();

    // ---------------- Phase 3: normalize --------------------------------
    // Same fixed-column striding -> mean/istd loaded ONCE per thread.
    // __ldcs: x's last use (evict-first); __stcs: don't pollute L2 with out.
    {
        const int qd = tid & 511;
        const float4 m = *reinterpret_cast<const float4*>(g_mean + 4 * qd);
        const float4 t = *reinterpret_cast<const float4*>(g_istd + 4 * qd);
        const float4* xp = reinterpret_cast<const float4*>(x);
        float4*       op = reinterpret_cast<float4*>(out);
        size_t i = (size_t)tid;

        #pragma unroll 1
        for (int b = 0; b < 6; ++b) {
            float4 buf[8];
            #pragma unroll
            for (int r = 0; r < 8; ++r) buf[r] = __ldcs(xp + i + (size_t)r * NTHREADS);
            #pragma unroll
            for (int r = 0; r < 8; ++r) {
                float4 o;
                o.x = (buf[r].x - m.x) * t.x;  o.y = (buf[r].y - m.y) * t.y;
                o.z = (buf[r].z - m.z) * t.z;  o.w = (buf[r].w - m.w) * t.w;
                __stcs(op + i + (size_t)r * NTHREADS, o);
            }
            i += (size_t)8 * NTHREADS;
        }
        {
            float4 buf[7];
            #pragma unroll
            for (int r = 0; r < 7; ++r) buf[r] = __ldcs(xp + i + (size_t)r * NTHREADS);
            #pragma unroll
            for (int r = 0; r < 7; ++r) {
                float4 o;
                o.x = (buf[r].x - m.x) * t.x;  o.y = (buf[r].y - m.y) * t.y;
                o.z = (buf[r].z - m.z) * t.z;  o.w = (buf[r].w - m.w) * t.w;
                __stcs(op + i + (size_t)r * NTHREADS, o);
            }
            i += (size_t)7 * NTHREADS;
        }
        if (tid < REM) {
            const float4 v = __ldcs(xp + i);
            float4 o;
            o.x = (v.x - m.x) * t.x;  o.y = (v.y - m.y) * t.y;
            o.z = (v.z - m.z) * t.z;  o.w = (v.w - m.w) * t.w;
            __stcs(op + i, o);
        }
    }
}

extern "C" void kernel_launch(void* const* d_in, const int* in_sizes, int n_in,
                              void* d_out, int out_size) {
    const float* x = (const float*)d_in[0];   // [8192, 2048] fp32
    float* out = (float*)d_out;               // [8192, 2048] fp32
    k_fused<<<GRID, TPB>>>(x, out);
}